// round 3
// baseline (speedup 1.0000x reference)
#include <cuda_runtime.h>
#include <math.h>
#include <stdint.h>

#define Bv 32
#define Tv 64
#define Sv 64
#define Ev 512
#define Hv 512
#define D2v 1024
#define Vv 32000
#define BH (Bv*Hv)              // 16384
#define GRID 128
#define NTHR 256
#define ATT_SCALE 0.0441941738241592f   // 1/sqrt(512)

// ---------------- scratch (device globals; no allocations allowed) ----------
__device__ float g_x[Bv*Tv*Ev];          // embedded inputs [b][t][e]
__device__ float g_h[2][2*BH];           // double-buffered hidden state
__device__ float g_c[2*BH];              // cell state
__device__ float g_hh[2*BH];             // hhat state
__device__ float g_gpart[2][2*Bv*4*Hv]; // gate GEMM partials (K-split 2)
__device__ float g_kpart[4][2*Bv*D2v];  // attention key partials (K-split 4)
__device__ float g_hcat[2*Bv*(Hv+D2v)]; // [h, ct] concat per (dir,b)
__device__ float g_hpart[8][2*BH];      // hhat GEMM partials (K-split 8)
__device__ float g_outf[Tv*BH];          // forward hhat sequence [t][b][u]
__device__ float g_outb[Tv*BH];          // backward hhat sequence (scan order)
__device__ float g_feat[Bv*Tv*2*Hv];     // packed features for fc
__device__ int   g_cnt;                  // grid barrier counter

// ---------------- embedding gather ----------------
__global__ void embed_kernel(const float* __restrict__ emb, const int* __restrict__ trg)
{
    int i = blockIdx.x*blockDim.x + threadIdx.x;
    if (i >= Bv*Tv*Ev) return;
    int e = i & 511;
    int bt = i >> 9;
    g_x[i] = emb[(long)trg[bt]*Ev + e];
}

// ---------------- init states + barrier reset ----------------
__global__ void init_kernel(const float* __restrict__ feed_init, const float* __restrict__ hid_init)
{
    int i = blockIdx.x*blockDim.x + threadIdx.x;
    if (i == 0) g_cnt = 0;
    if (i >= 2*BH) return;
    int u = i & 511;
    int dir = i >> 14;
    g_h[0][i] = hid_init[dir*1024 + u];
    g_c[i]    = hid_init[dir*1024 + 512 + u];
    g_hh[i]   = feed_init[dir*512 + u];
}

// ---------------- device-wide barrier (monotonic counter) ----------------
__device__ __forceinline__ void gbar(int& target)
{
    __threadfence();            // drain this thread's stores to L2
    __syncthreads();            // whole block's fences done
    if (threadIdx.x == 0) {
        atomicAdd(&g_cnt, 1);
        target += GRID;
        while (atomicAdd(&g_cnt, 0) < target) __nanosleep(64);
        __threadfence();        // invalidate L1 so fresh data is observed
    }
    __syncthreads();
}

// ---------------- fp32 tile inner product ----------------
__device__ __forceinline__ void tile_fma(const float As[32][20], const float Ws[64][20],
                                         float acc[2][4], int ty, int tx)
{
    #pragma unroll
    for (int kc = 0; kc < 16; kc++) {
        float a0 = As[ty][kc], a1 = As[ty+16][kc];
        #pragma unroll
        for (int j = 0; j < 4; j++) {
            float w = Ws[tx*4+j][kc];
            acc[0][j] = fmaf(a0, w, acc[0][j]);
            acc[1][j] = fmaf(a1, w, acc[1][j]);
        }
    }
}

// ---------------- persistent scan kernel ----------------
__global__ __launch_bounds__(NTHR) void scan_kernel(
    const float* __restrict__ src, const float* __restrict__ mask,
    const float* __restrict__ fWih, const float* __restrict__ fWhh,
    const float* __restrict__ fbih, const float* __restrict__ fbhh,
    const float* __restrict__ bWih, const float* __restrict__ bWhh,
    const float* __restrict__ bbih, const float* __restrict__ bbhh,
    const float* __restrict__ fattW, const float* __restrict__ fattb,
    const float* __restrict__ battW, const float* __restrict__ battb,
    const float* __restrict__ fahW, const float* __restrict__ fahb,
    const float* __restrict__ bahW, const float* __restrict__ bahb)
{
    __shared__ float As[32][20];
    __shared__ float Ws[64][20];
    __shared__ float ks[1024];
    __shared__ float wsm[64];
    __shared__ float red[256];

    int bx = blockIdx.x, tid = threadIdx.x;
    int ty = tid >> 4, tx = tid & 15;
    int target = 0;

    for (int t = 0; t < Tv; t++) {
        // ===== phase A: gates partial GEMM (dir x 32 ntiles x 2 ksplit) =====
        {
            int dir = bx >> 6, nt = (bx >> 1) & 31, kz = bx & 1;
            int n0 = nt * 64;
            int tsel = dir ? (Tv-1-t) : t;
            const float* Wih  = dir ? bWih : fWih;
            const float* Whh  = dir ? bWhh : fWhh;
            const float* hcur = &g_h[t&1][dir*BH];
            const float* hhat = &g_hh[dir*BH];
            float acc[2][4] = {};
            for (int k0 = kz*768; k0 < kz*768 + 768; k0 += 16) {
                for (int i = tid; i < 512; i += NTHR) {
                    int m = i >> 4, kc = i & 15, k = k0 + kc;
                    float v;
                    if (k < 512)       v = g_x[(m*Tv + tsel)*Ev + k];
                    else if (k < 1024) v = hhat[m*Hv + (k - 512)];
                    else               v = hcur[m*Hv + (k - 1024)];
                    As[m][kc] = v;
                }
                for (int i = tid; i < 1024; i += NTHR) {
                    int r = i >> 4, kc = i & 15, k = k0 + kc, col = n0 + r;
                    Ws[r][kc] = (k < 1024) ? Wih[col*1024 + k] : Whh[col*512 + (k-1024)];
                }
                __syncthreads();
                tile_fma(As, Ws, acc, ty, tx);
                __syncthreads();
            }
            float* outp = g_gpart[kz] + dir*Bv*4*Hv;
            #pragma unroll
            for (int j = 0; j < 4; j++) {
                outp[ty*2048      + n0 + tx*4 + j] = acc[0][j];
                outp[(ty+16)*2048 + n0 + tx*4 + j] = acc[1][j];
            }
        }
        gbar(target);

        // ===== phase B: LSTM pointwise =====
        {
            int i = bx*NTHR + tid;           // exactly 32768 threads
            int u = i & 511, b = (i >> 9) & 31, dir = i >> 14;
            const float* bih = dir ? bbih : fbih;
            const float* bhh = dir ? bbhh : fbhh;
            int base = (dir*Bv + b)*2048;
            float gi = 0.f, gf = 0.f, gg = 0.f, go = 0.f;
            #pragma unroll
            for (int z = 0; z < 2; z++) {
                const float* gp = g_gpart[z] + base;
                gi += gp[u]; gf += gp[512+u]; gg += gp[1024+u]; go += gp[1536+u];
            }
            gi += bih[u]      + bhh[u];
            gf += bih[512+u]  + bhh[512+u];
            gg += bih[1024+u] + bhh[1024+u];
            go += bih[1536+u] + bhh[1536+u];
            float si = 1.f/(1.f+expf(-gi));
            float sf = 1.f/(1.f+expf(-gf));
            float so = 1.f/(1.f+expf(-go));
            float c = sf * g_c[i] + si * tanhf(gg);
            float h = so * tanhf(c);
            if (dir) {
                float mm = mask[b*Tv + (Tv-1-t)];
                h *= mm; c *= mm;
            }
            g_c[i] = c;
            g_h[(t+1)&1][i] = h;
        }
        gbar(target);

        // ===== phase C: attention key proj partial (dir x 16 ntiles x 4 ksplit) =====
        {
            int dir = bx >> 6, nt = (bx >> 2) & 15, kz = bx & 3;
            int n0 = nt * 64;
            const float* W = dir ? battW : fattW;
            const float* h = &g_h[(t+1)&1][dir*BH];
            float acc[2][4] = {};
            for (int k0 = kz*128; k0 < kz*128 + 128; k0 += 16) {
                for (int i = tid; i < 512; i += NTHR) {
                    int m = i >> 4, kc = i & 15;
                    As[m][kc] = h[m*Hv + k0 + kc];
                }
                for (int i = tid; i < 1024; i += NTHR) {
                    int r = i >> 4, kc = i & 15;
                    Ws[r][kc] = W[(n0+r)*Hv + k0 + kc];
                }
                __syncthreads();
                tile_fma(As, Ws, acc, ty, tx);
                __syncthreads();
            }
            float* outp = g_kpart[kz] + dir*Bv*D2v;
            #pragma unroll
            for (int j = 0; j < 4; j++) {
                outp[ty*D2v      + n0 + tx*4 + j] = acc[0][j];
                outp[(ty+16)*D2v + n0 + tx*4 + j] = acc[1][j];
            }
        }
        gbar(target);

        // ===== phase D: attention scores/softmax/context (64 active blocks) =====
        if (bx < 64) {
            int dir = bx >> 5, b = bx & 31;
            const float* attb = dir ? battb : fattb;
            int kb = (dir*Bv + b)*D2v;
            for (int j = tid; j < 1024; j += NTHR)
                ks[j] = g_kpart[0][kb+j] + g_kpart[1][kb+j]
                      + g_kpart[2][kb+j] + g_kpart[3][kb+j] + attb[j];
            const float* h = &g_h[(t+1)&1][dir*BH + b*Hv];
            float* hcat = &g_hcat[(dir*Bv + b)*1536];
            for (int j = tid; j < 512; j += NTHR) hcat[j] = h[j];
            __syncthreads();

            const float* srcb = src + (long)b*Sv*D2v;
            {
                int s = tid >> 2, q = tid & 3;
                const float* row = srcb + s*D2v + q*256;
                const float* kq = ks + q*256;
                float p = 0.f;
                #pragma unroll 4
                for (int m = 0; m < 256; m++) p = fmaf(row[m], kq[m], p);
                red[tid] = p;
            }
            __syncthreads();
            if (tid < 64)
                wsm[tid] = (red[tid*4]+red[tid*4+1]+red[tid*4+2]+red[tid*4+3]) * ATT_SCALE;
            __syncthreads();
            if (tid < 32) {
                float a = wsm[tid], b2 = wsm[tid+32];
                float mx = fmaxf(a, b2);
                for (int o = 16; o; o >>= 1) mx = fmaxf(mx, __shfl_xor_sync(0xffffffffu, mx, o));
                float e0 = expf(a - mx), e1 = expf(b2 - mx);
                float sm = e0 + e1;
                for (int o = 16; o; o >>= 1) sm += __shfl_xor_sync(0xffffffffu, sm, o);
                float inv = 1.f / sm;
                wsm[tid] = e0 * inv; wsm[tid+32] = e1 * inv;
            }
            __syncthreads();
            float ct[4] = {};
            for (int s = 0; s < 64; s++) {
                float p = wsm[s];
                const float* row = srcb + s*D2v;
                #pragma unroll
                for (int r = 0; r < 4; r++) ct[r] = fmaf(p, row[r*256+tid], ct[r]);
            }
            #pragma unroll
            for (int r = 0; r < 4; r++) hcat[512 + r*256 + tid] = ct[r];
        }
        gbar(target);

        // ===== phase E: hhat GEMM partial (dir x 8 ntiles x 8 ksplit) =====
        // faithful swap: dir0 uses bahW, dir1 uses fahW
        {
            int dir = bx >> 6, nt = (bx >> 3) & 7, kz = bx & 7;
            int n0 = nt * 64;
            const float* W = dir ? fahW : bahW;
            const float* A = &g_hcat[dir*Bv*1536];
            float acc[2][4] = {};
            for (int k0 = kz*192; k0 < kz*192 + 192; k0 += 16) {
                for (int i = tid; i < 512; i += NTHR) {
                    int m = i >> 4, kc = i & 15;
                    As[m][kc] = A[m*1536 + k0 + kc];
                }
                for (int i = tid; i < 1024; i += NTHR) {
                    int r = i >> 4, kc = i & 15;
                    Ws[r][kc] = W[(n0+r)*1536 + k0 + kc];
                }
                __syncthreads();
                tile_fma(As, Ws, acc, ty, tx);
                __syncthreads();
            }
            float* outp = g_hpart[kz] + dir*BH;
            #pragma unroll
            for (int j = 0; j < 4; j++) {
                outp[ty*Hv      + n0 + tx*4 + j] = acc[0][j];
                outp[(ty+16)*Hv + n0 + tx*4 + j] = acc[1][j];
            }
        }
        gbar(target);

        // ===== phase F: hhat finalize =====
        {
            int i = bx*NTHR + tid;
            int u = i & 511, b = (i >> 9) & 31, dir = i >> 14;
            float s = dir ? fahb[u] : bahb[u];
            #pragma unroll
            for (int z = 0; z < 8; z++) s += g_hpart[z][i];
            float v = tanhf(s);
            g_hh[i] = v;
            if (dir == 0) g_outf[(t*Bv + b)*Hv + u] = v;
            else          g_outb[(t*Bv + b)*Hv + u] = v;
        }
        gbar(target);
    }
}

// ---------------- pack features: [f_out, shifted b_out] -------------------
__global__ void pack_kernel()
{
    int i = blockIdx.x*blockDim.x + threadIdx.x;
    if (i >= Bv*Tv*2*Hv) return;
    int j = i & 1023;
    int bt = i >> 10;
    int b = bt >> 6, t = bt & 63;
    float v;
    if (j < 512) v = g_outf[(t*Bv + b)*Hv + j];
    else         v = (t < Tv-2) ? g_outb[((t+2)*Bv + b)*Hv + (j-512)] : 0.f;
    g_feat[i] = v;
}

// ---------------- tf32 helpers ----------------
__device__ __forceinline__ float f2tf32(float x) {
    uint32_t o;
    asm("cvt.rna.tf32.f32 %0, %1;" : "=r"(o) : "f"(x));
    return __uint_as_float(o);
}

__device__ __forceinline__ void mma_tf32(float& d0, float& d1, float& d2, float& d3,
                                         uint32_t a0, uint32_t a1, uint32_t a2, uint32_t a3,
                                         uint32_t b0, uint32_t b1)
{
    asm volatile(
        "mma.sync.aligned.m16n8k8.row.col.f32.tf32.tf32.f32 "
        "{%0,%1,%2,%3},{%4,%5,%6,%7},{%8,%9},{%0,%1,%2,%3};"
        : "+f"(d0), "+f"(d1), "+f"(d2), "+f"(d3)
        : "r"(a0), "r"(a1), "r"(a2), "r"(a3), "r"(b0), "r"(b1));
}

// ---------------- output projection GEMM (tf32 tensor cores) ---------------
__global__ __launch_bounds__(256) void fc_kernel(
    const float* __restrict__ W, const float* __restrict__ bias, float* __restrict__ out)
{
    __shared__ float As[64][36];
    __shared__ float Bs[128][36];

    int n0 = blockIdx.x * 128;
    int m0 = blockIdx.y * 64;
    int tid  = threadIdx.x;
    int warp = tid >> 5, lane = tid & 31;
    int wm = warp >> 2, wn = warp & 3;
    int g  = lane >> 2;
    int tg = lane & 3;

    float acc[2][4][4];
    #pragma unroll
    for (int i = 0; i < 2; i++)
        #pragma unroll
        for (int j = 0; j < 4; j++)
            #pragma unroll
            for (int q = 0; q < 4; q++) acc[i][j][q] = 0.f;

    for (int k0 = 0; k0 < 1024; k0 += 32) {
        #pragma unroll
        for (int l = tid; l < 512; l += 256) {
            int r = l >> 3, kc = (l & 7) * 4;
            float4 v = *(const float4*)&g_feat[(m0 + r) * 1024 + k0 + kc];
            As[r][kc+0] = f2tf32(v.x); As[r][kc+1] = f2tf32(v.y);
            As[r][kc+2] = f2tf32(v.z); As[r][kc+3] = f2tf32(v.w);
        }
        #pragma unroll
        for (int l = tid; l < 1024; l += 256) {
            int r = l >> 3, kc = (l & 7) * 4;
            float4 v = *(const float4*)&W[(long)(n0 + r) * 1024 + k0 + kc];
            Bs[r][kc+0] = f2tf32(v.x); Bs[r][kc+1] = f2tf32(v.y);
            Bs[r][kc+2] = f2tf32(v.z); Bs[r][kc+3] = f2tf32(v.w);
        }
        __syncthreads();

        #pragma unroll
        for (int k8 = 0; k8 < 4; k8++) {
            int kb = k8 * 8;
            uint32_t a[2][4];
            #pragma unroll
            for (int mt = 0; mt < 2; mt++) {
                int rb = wm * 32 + mt * 16;
                a[mt][0] = __float_as_uint(As[rb + g    ][kb + tg    ]);
                a[mt][1] = __float_as_uint(As[rb + g + 8][kb + tg    ]);
                a[mt][2] = __float_as_uint(As[rb + g    ][kb + tg + 4]);
                a[mt][3] = __float_as_uint(As[rb + g + 8][kb + tg + 4]);
            }
            #pragma unroll
            for (int nt = 0; nt < 4; nt++) {
                int nb = wn * 32 + nt * 8 + g;
                uint32_t b0 = __float_as_uint(Bs[nb][kb + tg    ]);
                uint32_t b1 = __float_as_uint(Bs[nb][kb + tg + 4]);
                #pragma unroll
                for (int mt = 0; mt < 2; mt++)
                    mma_tf32(acc[mt][nt][0], acc[mt][nt][1], acc[mt][nt][2], acc[mt][nt][3],
                             a[mt][0], a[mt][1], a[mt][2], a[mt][3], b0, b1);
            }
        }
        __syncthreads();
    }

    #pragma unroll
    for (int mt = 0; mt < 2; mt++) {
        #pragma unroll
        for (int nt = 0; nt < 4; nt++) {
            long m_lo = m0 + wm * 32 + mt * 16 + g;
            long m_hi = m_lo + 8;
            int n = n0 + wn * 32 + nt * 8 + tg * 2;
            out[m_lo * Vv + n    ] = acc[mt][nt][0] + bias[n];
            out[m_lo * Vv + n + 1] = acc[mt][nt][1] + bias[n + 1];
            out[m_hi * Vv + n    ] = acc[mt][nt][2] + bias[n];
            out[m_hi * Vv + n + 1] = acc[mt][nt][3] + bias[n + 1];
        }
    }
}

// ---------------- launch ----------------
extern "C" void kernel_launch(void* const* d_in, const int* in_sizes, int n_in,
                              void* d_out, int out_size)
{
    const float* src   = (const float*)d_in[0];
    const int*   trg   = (const int*)  d_in[1];
    const float* mask  = (const float*)d_in[2];
    const float* emb   = (const float*)d_in[3];
    const float* fWih  = (const float*)d_in[4];
    const float* fWhh  = (const float*)d_in[5];
    const float* fbih  = (const float*)d_in[6];
    const float* fbhh  = (const float*)d_in[7];
    const float* bWih  = (const float*)d_in[8];
    const float* bWhh  = (const float*)d_in[9];
    const float* bbih  = (const float*)d_in[10];
    const float* bbhh  = (const float*)d_in[11];
    const float* fattW = (const float*)d_in[12];
    const float* fattb = (const float*)d_in[13];
    const float* battW = (const float*)d_in[14];
    const float* battb = (const float*)d_in[15];
    const float* fahW  = (const float*)d_in[16];
    const float* fahb  = (const float*)d_in[17];
    const float* bahW  = (const float*)d_in[18];
    const float* bahb  = (const float*)d_in[19];
    const float* fcW   = (const float*)d_in[20];
    const float* fcb   = (const float*)d_in[21];
    const float* feedi = (const float*)d_in[22];
    const float* hidi  = (const float*)d_in[23];
    float* out = (float*)d_out;

    embed_kernel<<<(Bv*Tv*Ev+255)/256, 256>>>(emb, trg);
    init_kernel<<<(2*BH+255)/256, 256>>>(feedi, hidi);
    scan_kernel<<<GRID, NTHR>>>(src, mask,
        fWih, fWhh, fbih, fbhh, bWih, bWhh, bbih, bbhh,
        fattW, fattb, battW, battb, fahW, fahb, bahW, bahb);
    pack_kernel<<<(Bv*Tv*2*Hv+255)/256, 256>>>();
    fc_kernel<<<dim3(Vv/128, (Bv*Tv)/64), 256>>>(fcW, fcb, out);
}

// round 9
// speedup vs baseline: 2.0119x; 2.0119x over previous
#include <cuda_runtime.h>
#include <math.h>
#include <stdint.h>

#define Bv 32
#define Tv 64
#define Sv 64
#define Ev 512
#define Hv 512
#define D2v 1024
#define Vv 32000
#define BH (Bv*Hv)              // 16384
#define ATT_SCALE 0.0441941738241592f   // 1/sqrt(512)

// ---------------- scratch (device globals) ----------------
__device__ float g_x[Bv*Tv*Ev];          // embedded inputs [b][t][e]
__device__ float g_h[2][2*BH];           // double-buffered hidden state
__device__ float g_c[2*BH];              // cell state
__device__ float g_hh[2*BH];             // hhat state
__device__ float g_k[2*Bv*D2v];          // attention key (full)
__device__ float g_hcat[2*Bv*(Hv+D2v)]; // [h, ct] per (dir,b)
__device__ float g_outf[Tv*BH];          // forward hhat sequence [t][b][u]
__device__ float g_outb[Tv*BH];          // backward hhat sequence (scan order)
__device__ float g_feat[Bv*Tv*2*Hv];     // packed features for fc

// ---------------- embedding gather ----------------
__global__ void embed_kernel(const float* __restrict__ emb, const int* __restrict__ trg)
{
    int i = blockIdx.x*blockDim.x + threadIdx.x;
    if (i >= Bv*Tv*Ev) return;
    int e = i & 511;
    int bt = i >> 9;
    g_x[i] = emb[(long)trg[bt]*Ev + e];
}

// ---------------- init states ----------------
__global__ void init_kernel(const float* __restrict__ feed_init, const float* __restrict__ hid_init)
{
    int i = blockIdx.x*blockDim.x + threadIdx.x;
    if (i >= 2*BH) return;
    int u = i & 511;
    int dir = i >> 14;
    g_h[0][i] = hid_init[dir*1024 + u];
    g_c[i]    = hid_init[dir*1024 + 512 + u];
    g_hh[i]   = feed_init[dir*512 + u];
}

// ================= K1: fused gates GEMM + LSTM pointwise ====================
// grid 128: dir(2) x utile(64 of 8 units). Block computes all 4 gates for its
// 8 units (32 W-rows) over full K=1536, then applies the LSTM update inline.
// W staged TRANSPOSED in smem: Ws_t[k][n] so compute reads one LDS.128.
__global__ __launch_bounds__(256) void step_gates_lstm(int t, const float* __restrict__ mask,
    const float* __restrict__ fWih, const float* __restrict__ fWhh,
    const float* __restrict__ fbih, const float* __restrict__ fbhh,
    const float* __restrict__ bWih, const float* __restrict__ bWhh,
    const float* __restrict__ bbih, const float* __restrict__ bbhh)
{
    __shared__ __align__(16) float As[32][36];
    __shared__ __align__(16) float Ws_t[32][36];   // [k][n]
    __shared__ float Gs[32][33];

    int bx = blockIdx.x, tid = threadIdx.x;
    int dir = bx >> 6, ut = bx & 63;
    int u0 = ut * 8;
    int tsel = dir ? (Tv-1-t) : t;
    const float* Wih   = dir ? bWih : fWih;
    const float* Whh   = dir ? bWhh : fWhh;
    const float* hprev = &g_h[t&1][dir*BH];
    const float* hhat  = &g_hh[dir*BH];

    int lr = tid >> 3;            // tile row 0..31
    int lq = (tid & 7) * 4;       // k offset within chunk
    int wrow = (lr >> 3)*512 + u0 + (lr & 7);   // actual weight row (gate-major)
    int m = lr, ng = tid & 7;     // compute mapping

    float4 pa, pw;
    pa = *(const float4*)&g_x[(m*Tv + tsel)*Ev + lq];
    pw = *(const float4*)&Wih[(long)wrow*1024 + lq];

    float acc[4] = {};
    for (int c = 0; c < 48; c++) {
        As[lr][lq  ] = pa.x; As[lr][lq+1] = pa.y; As[lr][lq+2] = pa.z; As[lr][lq+3] = pa.w;
        Ws_t[lq  ][lr] = pw.x; Ws_t[lq+1][lr] = pw.y;
        Ws_t[lq+2][lr] = pw.z; Ws_t[lq+3][lr] = pw.w;
        __syncthreads();
        if (c < 47) {
            int k = (c+1)*32 + lq;
            if (k < 512)        pa = *(const float4*)&g_x[(m*Tv + tsel)*Ev + k];
            else if (k < 1024)  pa = *(const float4*)&hhat[m*Hv + (k - 512)];
            else                pa = *(const float4*)&hprev[m*Hv + (k - 1024)];
            if (k < 1024)       pw = *(const float4*)&Wih[(long)wrow*1024 + k];
            else                pw = *(const float4*)&Whh[(long)wrow*512 + (k - 1024)];
        }
        #pragma unroll
        for (int k = 0; k < 32; k++) {
            float a = As[m][k];
            float4 w = *(const float4*)&Ws_t[k][ng*4];
            acc[0] = fmaf(a, w.x, acc[0]);
            acc[1] = fmaf(a, w.y, acc[1]);
            acc[2] = fmaf(a, w.z, acc[2]);
            acc[3] = fmaf(a, w.w, acc[3]);
        }
        __syncthreads();
    }
    #pragma unroll
    for (int j = 0; j < 4; j++) Gs[m][ng*4+j] = acc[j];
    __syncthreads();

    // LSTM pointwise: thread -> (b = tid&31, uu = tid>>5)
    {
        int b = tid & 31, uu = tid >> 5;
        int u = u0 + uu;
        const float* bih = dir ? bbih : fbih;
        const float* bhh = dir ? bbhh : fbhh;
        float gi = Gs[b][uu     ] + bih[u]        + bhh[u];
        float gf = Gs[b][8  + uu] + bih[512 + u]  + bhh[512 + u];
        float gg = Gs[b][16 + uu] + bih[1024 + u] + bhh[1024 + u];
        float go = Gs[b][24 + uu] + bih[1536 + u] + bhh[1536 + u];
        float si = 1.f/(1.f+expf(-gi));
        float sf = 1.f/(1.f+expf(-gf));
        float so = 1.f/(1.f+expf(-go));
        int idx = dir*BH + b*Hv + u;
        float c = sf * g_c[idx] + si * tanhf(gg);
        float h = so * tanhf(c);
        if (dir) {
            float mm = mask[b*Tv + (Tv-1-t)];
            h *= mm; c *= mm;
        }
        g_c[idx] = c;
        g_h[(t+1)&1][idx] = h;
    }
}

// ================= K2: attention key projection (full K) ====================
// grid 64: dir(2) x ntile(32 of 32 cols). K=512, 16 chunks.
__global__ __launch_bounds__(256) void step_kproj(int t,
    const float* __restrict__ fattW, const float* __restrict__ battW)
{
    __shared__ __align__(16) float As[32][36];
    __shared__ __align__(16) float Ws_t[32][36];

    int bx = blockIdx.x, tid = threadIdx.x;
    int dir = bx >> 5, nt = bx & 31;
    int n0 = nt * 32;
    const float* W = dir ? battW : fattW;
    const float* h = &g_h[(t+1)&1][dir*BH];

    int lr = tid >> 3, lq = (tid & 7) * 4;
    int m = lr, ng = tid & 7;

    float4 pa = *(const float4*)&h[m*Hv + lq];
    float4 pw = *(const float4*)&W[(n0+lr)*Hv + lq];

    float acc[4] = {};
    for (int c = 0; c < 16; c++) {
        As[lr][lq  ] = pa.x; As[lr][lq+1] = pa.y; As[lr][lq+2] = pa.z; As[lr][lq+3] = pa.w;
        Ws_t[lq  ][lr] = pw.x; Ws_t[lq+1][lr] = pw.y;
        Ws_t[lq+2][lr] = pw.z; Ws_t[lq+3][lr] = pw.w;
        __syncthreads();
        if (c < 15) {
            int k = (c+1)*32 + lq;
            pa = *(const float4*)&h[m*Hv + k];
            pw = *(const float4*)&W[(n0+lr)*Hv + k];
        }
        #pragma unroll
        for (int k = 0; k < 32; k++) {
            float a = As[m][k];
            float4 w = *(const float4*)&Ws_t[k][ng*4];
            acc[0] = fmaf(a, w.x, acc[0]);
            acc[1] = fmaf(a, w.y, acc[1]);
            acc[2] = fmaf(a, w.z, acc[2]);
            acc[3] = fmaf(a, w.w, acc[3]);
        }
        __syncthreads();
    }
    float4 o; o.x = acc[0]; o.y = acc[1]; o.z = acc[2]; o.w = acc[3];
    *(float4*)&g_k[(dir*Bv + m)*D2v + n0 + ng*4] = o;
}

// ================= K3: attention scores/softmax/context -> hcat =============
__global__ __launch_bounds__(256) void step_attn(int t, const float* __restrict__ src,
    const float* __restrict__ fattb, const float* __restrict__ battb)
{
    int b = blockIdx.x, dir = blockIdx.y;
    const float* attb = dir ? battb : fattb;
    __shared__ float ks[1024];
    __shared__ float wsm[64];
    __shared__ float red[256];
    int tid = threadIdx.x;
    int kb = (dir*Bv + b)*D2v;
    for (int j = tid; j < 1024; j += 256)
        ks[j] = g_k[kb+j] + attb[j];
    const float* h = &g_h[(t+1)&1][dir*BH + b*Hv];
    float* hcat = &g_hcat[(dir*Bv + b)*1536];
    for (int j = tid; j < 512; j += 256) hcat[j] = h[j];
    __syncthreads();

    const float* srcb = src + (long)b*Sv*D2v;
    {
        int s = tid >> 2, q = tid & 3;
        const float* row = srcb + s*D2v + q*256;
        const float* kq = ks + q*256;
        float p = 0.f;
        #pragma unroll 4
        for (int m2 = 0; m2 < 256; m2++) p = fmaf(row[m2], kq[m2], p);
        red[tid] = p;
    }
    __syncthreads();
    if (tid < 64)
        wsm[tid] = (red[tid*4]+red[tid*4+1]+red[tid*4+2]+red[tid*4+3]) * ATT_SCALE;
    __syncthreads();
    if (tid < 32) {
        float a = wsm[tid], b2 = wsm[tid+32];
        float mx = fmaxf(a, b2);
        for (int o = 16; o; o >>= 1) mx = fmaxf(mx, __shfl_xor_sync(0xffffffffu, mx, o));
        float e0 = expf(a - mx), e1 = expf(b2 - mx);
        float sm = e0 + e1;
        for (int o = 16; o; o >>= 1) sm += __shfl_xor_sync(0xffffffffu, sm, o);
        float inv = 1.f / sm;
        wsm[tid] = e0 * inv; wsm[tid+32] = e1 * inv;
    }
    __syncthreads();
    float ct[4] = {};
    for (int s = 0; s < 64; s++) {
        float p = wsm[s];
        const float* row = srcb + s*D2v;
        #pragma unroll
        for (int r = 0; r < 4; r++) ct[r] = fmaf(p, row[r*256+tid], ct[r]);
    }
    #pragma unroll
    for (int r = 0; r < 4; r++) hcat[512 + r*256 + tid] = ct[r];
}

// ================= K4: fused hhat GEMM + tanh + store =======================
// grid 32: dir(2) x utile(16 of 32 units). Full K=1536, 48 chunks.
// faithful swap: dir0 uses bahW/bahb, dir1 uses fahW/fahb
__global__ __launch_bounds__(256) void step_hhat(int t,
    const float* __restrict__ bahW, const float* __restrict__ bahb,
    const float* __restrict__ fahW, const float* __restrict__ fahb)
{
    __shared__ __align__(16) float As[32][36];
    __shared__ __align__(16) float Ws_t[32][36];

    int bx = blockIdx.x, tid = threadIdx.x;
    int dir = bx >> 4, utp = bx & 15;
    int u0 = utp * 32;
    const float* W = dir ? fahW : bahW;
    const float* bb = dir ? fahb : bahb;
    const float* A = &g_hcat[dir*Bv*1536];

    int lr = tid >> 3, lq = (tid & 7) * 4;
    int m = lr, ng = tid & 7;

    float4 pa = *(const float4*)&A[m*1536 + lq];
    float4 pw = *(const float4*)&W[(u0+lr)*1536 + lq];

    float acc[4] = {};
    for (int c = 0; c < 48; c++) {
        As[lr][lq  ] = pa.x; As[lr][lq+1] = pa.y; As[lr][lq+2] = pa.z; As[lr][lq+3] = pa.w;
        Ws_t[lq  ][lr] = pw.x; Ws_t[lq+1][lr] = pw.y;
        Ws_t[lq+2][lr] = pw.z; Ws_t[lq+3][lr] = pw.w;
        __syncthreads();
        if (c < 47) {
            int k = (c+1)*32 + lq;
            pa = *(const float4*)&A[m*1536 + k];
            pw = *(const float4*)&W[(u0+lr)*1536 + k];
        }
        #pragma unroll
        for (int k = 0; k < 32; k++) {
            float a = As[m][k];
            float4 w = *(const float4*)&Ws_t[k][ng*4];
            acc[0] = fmaf(a, w.x, acc[0]);
            acc[1] = fmaf(a, w.y, acc[1]);
            acc[2] = fmaf(a, w.z, acc[2]);
            acc[3] = fmaf(a, w.w, acc[3]);
        }
        __syncthreads();
    }
    #pragma unroll
    for (int j = 0; j < 4; j++) {
        int u = u0 + ng*4 + j;
        float v = tanhf(acc[j] + bb[u]);
        g_hh[(dir*Bv + m)*Hv + u] = v;
        if (dir == 0) g_outf[(t*Bv + m)*Hv + u] = v;
        else          g_outb[(t*Bv + m)*Hv + u] = v;
    }
}

// ---------------- pack features: [f_out, shifted b_out] -------------------
__global__ void pack_kernel()
{
    int i = blockIdx.x*blockDim.x + threadIdx.x;
    if (i >= Bv*Tv*2*Hv) return;
    int j = i & 1023;
    int bt = i >> 10;
    int b = bt >> 6, t = bt & 63;
    float v;
    if (j < 512) v = g_outf[(t*Bv + b)*Hv + j];
    else         v = (t < Tv-2) ? g_outb[((t+2)*Bv + b)*Hv + (j-512)] : 0.f;
    g_feat[i] = v;
}

// ---------------- tf32 helpers ----------------
__device__ __forceinline__ float f2tf32(float x) {
    uint32_t o;
    asm("cvt.rna.tf32.f32 %0, %1;" : "=r"(o) : "f"(x));
    return __uint_as_float(o);
}

__device__ __forceinline__ void mma_tf32(float& d0, float& d1, float& d2, float& d3,
                                         uint32_t a0, uint32_t a1, uint32_t a2, uint32_t a3,
                                         uint32_t b0, uint32_t b1)
{
    asm volatile(
        "mma.sync.aligned.m16n8k8.row.col.f32.tf32.tf32.f32 "
        "{%0,%1,%2,%3},{%4,%5,%6,%7},{%8,%9},{%0,%1,%2,%3};"
        : "+f"(d0), "+f"(d1), "+f"(d2), "+f"(d3)
        : "r"(a0), "r"(a1), "r"(a2), "r"(a3), "r"(b0), "r"(b1));
}

// ---------------- output projection GEMM (tf32 tensor cores) ---------------
__global__ __launch_bounds__(256) void fc_kernel(
    const float* __restrict__ W, const float* __restrict__ bias, float* __restrict__ out)
{
    __shared__ float As[64][36];
    __shared__ float Bs[128][36];

    int n0 = blockIdx.x * 128;
    int m0 = blockIdx.y * 64;
    int tid  = threadIdx.x;
    int warp = tid >> 5, lane = tid & 31;
    int wm = warp >> 2, wn = warp & 3;
    int g  = lane >> 2;
    int tg = lane & 3;

    float acc[2][4][4];
    #pragma unroll
    for (int i = 0; i < 2; i++)
        #pragma unroll
        for (int j = 0; j < 4; j++)
            #pragma unroll
            for (int q = 0; q < 4; q++) acc[i][j][q] = 0.f;

    for (int k0 = 0; k0 < 1024; k0 += 32) {
        #pragma unroll
        for (int l = tid; l < 512; l += 256) {
            int r = l >> 3, kc = (l & 7) * 4;
            float4 v = *(const float4*)&g_feat[(m0 + r) * 1024 + k0 + kc];
            As[r][kc+0] = f2tf32(v.x); As[r][kc+1] = f2tf32(v.y);
            As[r][kc+2] = f2tf32(v.z); As[r][kc+3] = f2tf32(v.w);
        }
        #pragma unroll
        for (int l = tid; l < 1024; l += 256) {
            int r = l >> 3, kc = (l & 7) * 4;
            float4 v = *(const float4*)&W[(long)(n0 + r) * 1024 + k0 + kc];
            Bs[r][kc+0] = f2tf32(v.x); Bs[r][kc+1] = f2tf32(v.y);
            Bs[r][kc+2] = f2tf32(v.z); Bs[r][kc+3] = f2tf32(v.w);
        }
        __syncthreads();

        #pragma unroll
        for (int k8 = 0; k8 < 4; k8++) {
            int kb = k8 * 8;
            uint32_t a[2][4];
            #pragma unroll
            for (int mt = 0; mt < 2; mt++) {
                int rb = wm * 32 + mt * 16;
                a[mt][0] = __float_as_uint(As[rb + g    ][kb + tg    ]);
                a[mt][1] = __float_as_uint(As[rb + g + 8][kb + tg    ]);
                a[mt][2] = __float_as_uint(As[rb + g    ][kb + tg + 4]);
                a[mt][3] = __float_as_uint(As[rb + g + 8][kb + tg + 4]);
            }
            #pragma unroll
            for (int nt = 0; nt < 4; nt++) {
                int nb = wn * 32 + nt * 8 + g;
                uint32_t b0 = __float_as_uint(Bs[nb][kb + tg    ]);
                uint32_t b1 = __float_as_uint(Bs[nb][kb + tg + 4]);
                #pragma unroll
                for (int mt = 0; mt < 2; mt++)
                    mma_tf32(acc[mt][nt][0], acc[mt][nt][1], acc[mt][nt][2], acc[mt][nt][3],
                             a[mt][0], a[mt][1], a[mt][2], a[mt][3], b0, b1);
            }
        }
        __syncthreads();
    }

    #pragma unroll
    for (int mt = 0; mt < 2; mt++) {
        #pragma unroll
        for (int nt = 0; nt < 4; nt++) {
            long m_lo = m0 + wm * 32 + mt * 16 + g;
            long m_hi = m_lo + 8;
            int n = n0 + wn * 32 + nt * 8 + tg * 2;
            out[m_lo * Vv + n    ] = acc[mt][nt][0] + bias[n];
            out[m_lo * Vv + n + 1] = acc[mt][nt][1] + bias[n + 1];
            out[m_hi * Vv + n    ] = acc[mt][nt][2] + bias[n];
            out[m_hi * Vv + n + 1] = acc[mt][nt][3] + bias[n + 1];
        }
    }
}

// ---------------- launch ----------------
extern "C" void kernel_launch(void* const* d_in, const int* in_sizes, int n_in,
                              void* d_out, int out_size)
{
    const float* src   = (const float*)d_in[0];
    const int*   trg   = (const int*)  d_in[1];
    const float* mask  = (const float*)d_in[2];
    const float* emb   = (const float*)d_in[3];
    const float* fWih  = (const float*)d_in[4];
    const float* fWhh  = (const float*)d_in[5];
    const float* fbih  = (const float*)d_in[6];
    const float* fbhh  = (const float*)d_in[7];
    const float* bWih  = (const float*)d_in[8];
    const float* bWhh  = (const float*)d_in[9];
    const float* bbih  = (const float*)d_in[10];
    const float* bbhh  = (const float*)d_in[11];
    const float* fattW = (const float*)d_in[12];
    const float* fattb = (const float*)d_in[13];
    const float* battW = (const float*)d_in[14];
    const float* battb = (const float*)d_in[15];
    const float* fahW  = (const float*)d_in[16];
    const float* fahb  = (const float*)d_in[17];
    const float* bahW  = (const float*)d_in[18];
    const float* bahb  = (const float*)d_in[19];
    const float* fcW   = (const float*)d_in[20];
    const float* fcb   = (const float*)d_in[21];
    const float* feedi = (const float*)d_in[22];
    const float* hidi  = (const float*)d_in[23];
    float* out = (float*)d_out;

    embed_kernel<<<(Bv*Tv*Ev+255)/256, 256>>>(emb, trg);
    init_kernel<<<(2*BH+255)/256, 256>>>(feedi, hidi);
    for (int t = 0; t < Tv; t++) {
        step_gates_lstm<<<128, 256>>>(t, mask, fWih, fWhh, fbih, fbhh,
                                      bWih, bWhh, bbih, bbhh);
        step_kproj<<<64, 256>>>(t, fattW, battW);
        step_attn<<<dim3(Bv,2), 256>>>(t, src, fattb, battb);
        step_hhat<<<32, 256>>>(t, bahW, bahb, fahW, fahb);
    }
    pack_kernel<<<(Bv*Tv*2*Hv+255)/256, 256>>>();
    fc_kernel<<<dim3(Vv/128, (Bv*Tv)/64), 256>>>(fcW, fcb, out);
}

// round 10
// speedup vs baseline: 2.7597x; 1.3717x over previous
#include <cuda_runtime.h>
#include <math.h>
#include <stdint.h>

#define Bv 32
#define Tv 64
#define Sv 64
#define Ev 512
#define Hv 512
#define D2v 1024
#define Vv 32000
#define BH (Bv*Hv)              // 16384
#define ATT_SCALE 0.0441941738241592f   // 1/sqrt(512)

// ---------------- scratch (device globals) ----------------
__device__ float g_x[Bv*Tv*Ev];          // embedded inputs [b][t][e]
__device__ float g_h[2][2*BH];           // double-buffered hidden state
__device__ float g_c[2*BH];              // cell state
__device__ float g_hh[2*BH];             // hhat state
__device__ float g_P[2*2048*512];        // P[dir][bs][u]  = attW^T @ src
__device__ float g_Q[2*2048*512];        // Q[dir][bs][u]  = ahW_c @ src
__device__ float g_qv[2*2048];           // q[dir][bs]     = attb . src
__device__ float g_outf[Tv*BH];          // forward hhat sequence [t][b][u]
__device__ float g_outb[Tv*BH];          // backward hhat sequence (scan order)
__device__ float g_feat[Bv*Tv*2*Hv];     // packed features for fc

// ---------------- embedding gather ----------------
__global__ void embed_kernel(const float* __restrict__ emb, const int* __restrict__ trg)
{
    int i = blockIdx.x*blockDim.x + threadIdx.x;
    if (i >= Bv*Tv*Ev) return;
    int e = i & 511;
    int bt = i >> 9;
    g_x[i] = emb[(long)trg[bt]*Ev + e];
}

// ---------------- init states ----------------
__global__ void init_kernel(const float* __restrict__ feed_init, const float* __restrict__ hid_init)
{
    int i = blockIdx.x*blockDim.x + threadIdx.x;
    if (i >= 2*BH) return;
    int u = i & 511;
    int dir = i >> 14;
    g_h[0][i] = hid_init[dir*1024 + u];
    g_c[i]    = hid_init[dir*1024 + 512 + u];
    g_hh[i]   = feed_init[dir*512 + u];
}

// ============ precompute P[dir][bs][u] = sum_d src[bs][d] * attW[d][u] =====
// attW is [D2=1024][H=512] row-major (k-major for this GEMM: B[k][n] direct).
__global__ __launch_bounds__(256) void prep_P(const float* __restrict__ src,
    const float* __restrict__ fattW, const float* __restrict__ battW)
{
    __shared__ float As[32][17];
    __shared__ float Bs[16][68];
    int m0 = blockIdx.x*32;        // bs tile
    int n0 = blockIdx.y*64;        // u tile
    int dir = blockIdx.z;
    const float* W = dir ? battW : fattW;
    int tid = threadIdx.x, ty = tid>>4, tx = tid&15;
    float acc[2][4] = {};
    for (int k0 = 0; k0 < 1024; k0 += 16) {
        for (int i = tid; i < 512; i += 256) {
            int m = i>>4, kc = i&15;
            As[m][kc] = src[(long)(m0+m)*1024 + k0 + kc];
        }
        {
            int kc = tid>>4, nq = (tid&15)*4;
            float4 v = *(const float4*)&W[(long)(k0+kc)*512 + n0 + nq];
            Bs[kc][nq] = v.x; Bs[kc][nq+1] = v.y; Bs[kc][nq+2] = v.z; Bs[kc][nq+3] = v.w;
        }
        __syncthreads();
        #pragma unroll
        for (int kc = 0; kc < 16; kc++) {
            float a0 = As[ty][kc], a1 = As[ty+16][kc];
            #pragma unroll
            for (int j = 0; j < 4; j++) {
                float w = Bs[kc][tx*4+j];
                acc[0][j] = fmaf(a0, w, acc[0][j]);
                acc[1][j] = fmaf(a1, w, acc[1][j]);
            }
        }
        __syncthreads();
    }
    #pragma unroll
    for (int j = 0; j < 4; j++) {
        g_P[(long)(dir*2048 + m0+ty   )*512 + n0 + tx*4 + j] = acc[0][j];
        g_P[(long)(dir*2048 + m0+ty+16)*512 + n0 + tx*4 + j] = acc[1][j];
    }
}

// ============ precompute Q[dir][bs][u] = sum_d src[bs][d] * ahW[u][512+d] ===
// dir0 uses bahW, dir1 uses fahW (faithful swap). ahW is [512][1536].
__global__ __launch_bounds__(256) void prep_Q(const float* __restrict__ src,
    const float* __restrict__ bahW, const float* __restrict__ fahW)
{
    __shared__ float As[32][17];
    __shared__ float Bs[16][68];
    int m0 = blockIdx.x*32;
    int n0 = blockIdx.y*64;
    int dir = blockIdx.z;
    const float* W = dir ? fahW : bahW;
    int tid = threadIdx.x, ty = tid>>4, tx = tid&15;
    float acc[2][4] = {};
    for (int k0 = 0; k0 < 1024; k0 += 16) {
        for (int i = tid; i < 512; i += 256) {
            int m = i>>4, kc = i&15;
            As[m][kc] = src[(long)(m0+m)*1024 + k0 + kc];
        }
        {
            int n = tid>>2, kq = (tid&3)*4;
            float4 v = *(const float4*)&W[(long)(n0+n)*1536 + 512 + k0 + kq];
            Bs[kq][n] = v.x; Bs[kq+1][n] = v.y; Bs[kq+2][n] = v.z; Bs[kq+3][n] = v.w;
        }
        __syncthreads();
        #pragma unroll
        for (int kc = 0; kc < 16; kc++) {
            float a0 = As[ty][kc], a1 = As[ty+16][kc];
            #pragma unroll
            for (int j = 0; j < 4; j++) {
                float w = Bs[kc][tx*4+j];
                acc[0][j] = fmaf(a0, w, acc[0][j]);
                acc[1][j] = fmaf(a1, w, acc[1][j]);
            }
        }
        __syncthreads();
    }
    #pragma unroll
    for (int j = 0; j < 4; j++) {
        g_Q[(long)(dir*2048 + m0+ty   )*512 + n0 + tx*4 + j] = acc[0][j];
        g_Q[(long)(dir*2048 + m0+ty+16)*512 + n0 + tx*4 + j] = acc[1][j];
    }
}

// ============ precompute q[dir][bs] = attb . src[bs] ========================
__global__ __launch_bounds__(256) void prep_q(const float* __restrict__ src,
    const float* __restrict__ fattb, const float* __restrict__ battb)
{
    int dir = blockIdx.y;
    const float* attb = dir ? battb : fattb;
    int warp = threadIdx.x >> 5, lane = threadIdx.x & 31;
    int bs = blockIdx.x*8 + warp;
    const float4* row = (const float4*)&src[(long)bs*1024];
    const float4* bb  = (const float4*)attb;
    float p = 0.f;
    for (int i = lane; i < 256; i += 32) {
        float4 a = row[i], b = bb[i];
        p += a.x*b.x + a.y*b.y + a.z*b.z + a.w*b.w;
    }
    for (int o = 16; o; o >>= 1) p += __shfl_xor_sync(0xffffffffu, p, o);
    if (lane == 0) g_qv[dir*2048 + bs] = p;
}

// ================= K1: fused gates GEMM + LSTM pointwise ====================
// grid 128: dir(2) x utile(64 of 8 units). Full K=1536, transposed-W smem.
__global__ __launch_bounds__(256) void step_gates_lstm(int t, const float* __restrict__ mask,
    const float* __restrict__ fWih, const float* __restrict__ fWhh,
    const float* __restrict__ fbih, const float* __restrict__ fbhh,
    const float* __restrict__ bWih, const float* __restrict__ bWhh,
    const float* __restrict__ bbih, const float* __restrict__ bbhh)
{
    __shared__ __align__(16) float As[32][36];
    __shared__ __align__(16) float Ws_t[32][36];   // [k][n]
    __shared__ float Gs[32][33];

    int bx = blockIdx.x, tid = threadIdx.x;
    int dir = bx >> 6, ut = bx & 63;
    int u0 = ut * 8;
    int tsel = dir ? (Tv-1-t) : t;
    const float* Wih   = dir ? bWih : fWih;
    const float* Whh   = dir ? bWhh : fWhh;
    const float* hprev = &g_h[t&1][dir*BH];
    const float* hhat  = &g_hh[dir*BH];

    int lr = tid >> 3;            // tile row 0..31
    int lq = (tid & 7) * 4;       // k offset within chunk
    int wrow = (lr >> 3)*512 + u0 + (lr & 7);   // weight row (gate-major)
    int m = lr, ng = tid & 7;

    float4 pa, pw;
    pa = *(const float4*)&g_x[(m*Tv + tsel)*Ev + lq];
    pw = *(const float4*)&Wih[(long)wrow*1024 + lq];

    float acc[4] = {};
    for (int c = 0; c < 48; c++) {
        As[lr][lq  ] = pa.x; As[lr][lq+1] = pa.y; As[lr][lq+2] = pa.z; As[lr][lq+3] = pa.w;
        Ws_t[lq  ][lr] = pw.x; Ws_t[lq+1][lr] = pw.y;
        Ws_t[lq+2][lr] = pw.z; Ws_t[lq+3][lr] = pw.w;
        __syncthreads();
        if (c < 47) {
            int k = (c+1)*32 + lq;
            if (k < 512)        pa = *(const float4*)&g_x[(m*Tv + tsel)*Ev + k];
            else if (k < 1024)  pa = *(const float4*)&hhat[m*Hv + (k - 512)];
            else                pa = *(const float4*)&hprev[m*Hv + (k - 1024)];
            if (k < 1024)       pw = *(const float4*)&Wih[(long)wrow*1024 + k];
            else                pw = *(const float4*)&Whh[(long)wrow*512 + (k - 1024)];
        }
        #pragma unroll
        for (int k = 0; k < 32; k++) {
            float a = As[m][k];
            float4 w = *(const float4*)&Ws_t[k][ng*4];
            acc[0] = fmaf(a, w.x, acc[0]);
            acc[1] = fmaf(a, w.y, acc[1]);
            acc[2] = fmaf(a, w.z, acc[2]);
            acc[3] = fmaf(a, w.w, acc[3]);
        }
        __syncthreads();
    }
    #pragma unroll
    for (int j = 0; j < 4; j++) Gs[m][ng*4+j] = acc[j];
    __syncthreads();

    {
        int b = tid & 31, uu = tid >> 5;
        int u = u0 + uu;
        const float* bih = dir ? bbih : fbih;
        const float* bhh = dir ? bbhh : fbhh;
        float gi = Gs[b][uu     ] + bih[u]        + bhh[u];
        float gf = Gs[b][8  + uu] + bih[512 + u]  + bhh[512 + u];
        float gg = Gs[b][16 + uu] + bih[1024 + u] + bhh[1024 + u];
        float go = Gs[b][24 + uu] + bih[1536 + u] + bhh[1536 + u];
        float si = 1.f/(1.f+expf(-gi));
        float sf = 1.f/(1.f+expf(-gf));
        float so = 1.f/(1.f+expf(-go));
        int idx = dir*BH + b*Hv + u;
        float c = sf * g_c[idx] + si * tanhf(gg);
        float h = so * tanhf(c);
        if (dir) {
            float mm = mask[b*Tv + (Tv-1-t)];
            h *= mm; c *= mm;
        }
        g_c[idx] = c;
        g_h[(t+1)&1][idx] = h;
    }
}

// ====== K2: fused attention scores/softmax + hhat(U+V) per (b,dir) =========
// scores:  w[s] = (h . P[b,s] + qv[b,s]) * scale ;  p = softmax(w)
// hhat[u] = tanh( sum_v ahW[u][v] h[v]  +  sum_s p[s] Q[b,s][u]  + ahb[u] )
// dir0 uses bahW/bahb, dir1 uses fahW/fahb (faithful swap).
__global__ __launch_bounds__(256) void step_attn_hhat(int t,
    const float* __restrict__ bahW, const float* __restrict__ bahb,
    const float* __restrict__ fahW, const float* __restrict__ fahb)
{
    __shared__ __align__(16) float hs[512];
    __shared__ float red[256];
    __shared__ float wsm[64];

    int b = blockIdx.x, dir = blockIdx.y;
    int tid = threadIdx.x;
    const float* ahW = dir ? fahW : bahW;
    const float* ahb = dir ? fahb : bahb;
    int base = dir*Bv + b;                 // (dir,b) flat
    long pqBase = (long)(dir*2048 + b*64)*512;

    const float* h = &g_h[(t+1)&1][dir*BH + b*Hv];
    hs[tid]       = h[tid];
    hs[tid + 256] = h[tid + 256];
    __syncthreads();

    // scores: 4 threads per s, 128-elem partials
    {
        int s = tid >> 2, qid = tid & 3;
        const float4* pr = (const float4*)&g_P[pqBase + (long)s*512 + qid*128];
        const float4* hq = (const float4*)&hs[qid*128];
        float p = 0.f;
        #pragma unroll 4
        for (int i = 0; i < 32; i++) {
            float4 a = pr[i], x = hq[i];
            p += a.x*x.x + a.y*x.y + a.z*x.z + a.w*x.w;
        }
        red[tid] = p;
    }
    __syncthreads();
    if (tid < 64)
        wsm[tid] = (red[tid*4]+red[tid*4+1]+red[tid*4+2]+red[tid*4+3]
                    + g_qv[dir*2048 + b*64 + tid]) * ATT_SCALE;
    __syncthreads();
    if (tid < 32) {
        float a = wsm[tid], b2 = wsm[tid+32];
        float mx = fmaxf(a, b2);
        for (int o = 16; o; o >>= 1) mx = fmaxf(mx, __shfl_xor_sync(0xffffffffu, mx, o));
        float e0 = expf(a - mx), e1 = expf(b2 - mx);
        float sm = e0 + e1;
        for (int o = 16; o; o >>= 1) sm += __shfl_xor_sync(0xffffffffu, sm, o);
        float inv = 1.f / sm;
        wsm[tid] = e0 * inv; wsm[tid+32] = e1 * inv;
    }
    __syncthreads();

    // V = sum_s p[s] * Q[b,s][:]  (two u's per thread: tid, tid+256)
    float v0 = 0.f, v1 = 0.f;
    {
        const float* Qb = &g_Q[pqBase];
        #pragma unroll 4
        for (int s = 0; s < 64; s++) {
            float ps = wsm[s];
            v0 = fmaf(ps, Qb[(long)s*512 + tid      ], v0);
            v1 = fmaf(ps, Qb[(long)s*512 + tid + 256], v1);
        }
    }

    // U = ahW[:, :512] @ h   (rows tid and tid+256)
    float u0a = 0.f, u0b = 0.f, u0c = 0.f, u0d = 0.f;
    float u1a = 0.f, u1b = 0.f, u1c = 0.f, u1d = 0.f;
    {
        const float4* w0 = (const float4*)&ahW[(long)tid*1536];
        const float4* w1 = (const float4*)&ahW[(long)(tid+256)*1536];
        const float4* hv = (const float4*)hs;
        #pragma unroll 8
        for (int i = 0; i < 128; i++) {
            float4 x = hv[i];
            float4 a = w0[i];
            float4 c = w1[i];
            u0a = fmaf(a.x, x.x, u0a); u0b = fmaf(a.y, x.y, u0b);
            u0c = fmaf(a.z, x.z, u0c); u0d = fmaf(a.w, x.w, u0d);
            u1a = fmaf(c.x, x.x, u1a); u1b = fmaf(c.y, x.y, u1b);
            u1c = fmaf(c.z, x.z, u1c); u1d = fmaf(c.w, x.w, u1d);
        }
    }
    float r0 = tanhf((u0a+u0b) + (u0c+u0d) + v0 + ahb[tid]);
    float r1 = tanhf((u1a+u1b) + (u1c+u1d) + v1 + ahb[tid+256]);

    g_hh[base*Hv + tid]       = r0;
    g_hh[base*Hv + tid + 256] = r1;
    if (dir == 0) {
        g_outf[(t*Bv + b)*Hv + tid]       = r0;
        g_outf[(t*Bv + b)*Hv + tid + 256] = r1;
    } else {
        g_outb[(t*Bv + b)*Hv + tid]       = r0;
        g_outb[(t*Bv + b)*Hv + tid + 256] = r1;
    }
}

// ---------------- pack features: [f_out, shifted b_out] -------------------
__global__ void pack_kernel()
{
    int i = blockIdx.x*blockDim.x + threadIdx.x;
    if (i >= Bv*Tv*2*Hv) return;
    int j = i & 1023;
    int bt = i >> 10;
    int b = bt >> 6, t = bt & 63;
    float v;
    if (j < 512) v = g_outf[(t*Bv + b)*Hv + j];
    else         v = (t < Tv-2) ? g_outb[((t+2)*Bv + b)*Hv + (j-512)] : 0.f;
    g_feat[i] = v;
}

// ---------------- tf32 helpers ----------------
__device__ __forceinline__ float f2tf32(float x) {
    uint32_t o;
    asm("cvt.rna.tf32.f32 %0, %1;" : "=r"(o) : "f"(x));
    return __uint_as_float(o);
}

__device__ __forceinline__ void mma_tf32(float& d0, float& d1, float& d2, float& d3,
                                         uint32_t a0, uint32_t a1, uint32_t a2, uint32_t a3,
                                         uint32_t b0, uint32_t b1)
{
    asm volatile(
        "mma.sync.aligned.m16n8k8.row.col.f32.tf32.tf32.f32 "
        "{%0,%1,%2,%3},{%4,%5,%6,%7},{%8,%9},{%0,%1,%2,%3};"
        : "+f"(d0), "+f"(d1), "+f"(d2), "+f"(d3)
        : "r"(a0), "r"(a1), "r"(a2), "r"(a3), "r"(b0), "r"(b1));
}

// ---------------- output projection GEMM (tf32 tensor cores) ---------------
__global__ __launch_bounds__(256) void fc_kernel(
    const float* __restrict__ W, const float* __restrict__ bias, float* __restrict__ out)
{
    __shared__ float As[64][36];
    __shared__ float Bs[128][36];

    int n0 = blockIdx.x * 128;
    int m0 = blockIdx.y * 64;
    int tid  = threadIdx.x;
    int warp = tid >> 5, lane = tid & 31;
    int wm = warp >> 2, wn = warp & 3;
    int g  = lane >> 2;
    int tg = lane & 3;

    float acc[2][4][4];
    #pragma unroll
    for (int i = 0; i < 2; i++)
        #pragma unroll
        for (int j = 0; j < 4; j++)
            #pragma unroll
            for (int q = 0; q < 4; q++) acc[i][j][q] = 0.f;

    for (int k0 = 0; k0 < 1024; k0 += 32) {
        #pragma unroll
        for (int l = tid; l < 512; l += 256) {
            int r = l >> 3, kc = (l & 7) * 4;
            float4 v = *(const float4*)&g_feat[(m0 + r) * 1024 + k0 + kc];
            As[r][kc+0] = f2tf32(v.x); As[r][kc+1] = f2tf32(v.y);
            As[r][kc+2] = f2tf32(v.z); As[r][kc+3] = f2tf32(v.w);
        }
        #pragma unroll
        for (int l = tid; l < 1024; l += 256) {
            int r = l >> 3, kc = (l & 7) * 4;
            float4 v = *(const float4*)&W[(long)(n0 + r) * 1024 + k0 + kc];
            Bs[r][kc+0] = f2tf32(v.x); Bs[r][kc+1] = f2tf32(v.y);
            Bs[r][kc+2] = f2tf32(v.z); Bs[r][kc+3] = f2tf32(v.w);
        }
        __syncthreads();

        #pragma unroll
        for (int k8 = 0; k8 < 4; k8++) {
            int kb = k8 * 8;
            uint32_t a[2][4];
            #pragma unroll
            for (int mt = 0; mt < 2; mt++) {
                int rb = wm * 32 + mt * 16;
                a[mt][0] = __float_as_uint(As[rb + g    ][kb + tg    ]);
                a[mt][1] = __float_as_uint(As[rb + g + 8][kb + tg    ]);
                a[mt][2] = __float_as_uint(As[rb + g    ][kb + tg + 4]);
                a[mt][3] = __float_as_uint(As[rb + g + 8][kb + tg + 4]);
            }
            #pragma unroll
            for (int nt = 0; nt < 4; nt++) {
                int nb = wn * 32 + nt * 8 + g;
                uint32_t b0 = __float_as_uint(Bs[nb][kb + tg    ]);
                uint32_t b1 = __float_as_uint(Bs[nb][kb + tg + 4]);
                #pragma unroll
                for (int mt = 0; mt < 2; mt++)
                    mma_tf32(acc[mt][nt][0], acc[mt][nt][1], acc[mt][nt][2], acc[mt][nt][3],
                             a[mt][0], a[mt][1], a[mt][2], a[mt][3], b0, b1);
            }
        }
        __syncthreads();
    }

    #pragma unroll
    for (int mt = 0; mt < 2; mt++) {
        #pragma unroll
        for (int nt = 0; nt < 4; nt++) {
            long m_lo = m0 + wm * 32 + mt * 16 + g;
            long m_hi = m_lo + 8;
            int n = n0 + wn * 32 + nt * 8 + tg * 2;
            out[m_lo * Vv + n    ] = acc[mt][nt][0] + bias[n];
            out[m_lo * Vv + n + 1] = acc[mt][nt][1] + bias[n + 1];
            out[m_hi * Vv + n    ] = acc[mt][nt][2] + bias[n];
            out[m_hi * Vv + n + 1] = acc[mt][nt][3] + bias[n + 1];
        }
    }
}

// ---------------- launch ----------------
extern "C" void kernel_launch(void* const* d_in, const int* in_sizes, int n_in,
                              void* d_out, int out_size)
{
    const float* src   = (const float*)d_in[0];
    const int*   trg   = (const int*)  d_in[1];
    const float* mask  = (const float*)d_in[2];
    const float* emb   = (const float*)d_in[3];
    const float* fWih  = (const float*)d_in[4];
    const float* fWhh  = (const float*)d_in[5];
    const float* fbih  = (const float*)d_in[6];
    const float* fbhh  = (const float*)d_in[7];
    const float* bWih  = (const float*)d_in[8];
    const float* bWhh  = (const float*)d_in[9];
    const float* bbih  = (const float*)d_in[10];
    const float* bbhh  = (const float*)d_in[11];
    const float* fattW = (const float*)d_in[12];
    const float* fattb = (const float*)d_in[13];
    const float* battW = (const float*)d_in[14];
    const float* battb = (const float*)d_in[15];
    const float* fahW  = (const float*)d_in[16];
    const float* fahb  = (const float*)d_in[17];
    const float* bahW  = (const float*)d_in[18];
    const float* bahb  = (const float*)d_in[19];
    const float* fcW   = (const float*)d_in[20];
    const float* fcb   = (const float*)d_in[21];
    const float* feedi = (const float*)d_in[22];
    const float* hidi  = (const float*)d_in[23];
    float* out = (float*)d_out;

    embed_kernel<<<(Bv*Tv*Ev+255)/256, 256>>>(emb, trg);
    init_kernel<<<(2*BH+255)/256, 256>>>(feedi, hidi);
    prep_P<<<dim3(64, 8, 2), 256>>>(src, fattW, battW);
    prep_Q<<<dim3(64, 8, 2), 256>>>(src, bahW, fahW);
    prep_q<<<dim3(256, 2), 256>>>(src, fattb, battb);
    for (int t = 0; t < Tv; t++) {
        step_gates_lstm<<<128, 256>>>(t, mask, fWih, fWhh, fbih, fbhh,
                                      bWih, bWhh, bbih, bbhh);
        step_attn_hhat<<<dim3(Bv, 2), 256>>>(t, bahW, bahb, fahW, fahb);
    }
    pack_kernel<<<(Bv*Tv*2*Hv+255)/256, 256>>>();
    fc_kernel<<<dim3(Vv/128, (Bv*Tv)/64), 256>>>(fcW, fcb, out);
}